// round 3
// baseline (speedup 1.0000x reference)
#include <cuda_runtime.h>

#define FEAT 128
#define RPW 16            // rows per work chunk (one warp per chunk)
#define WARPS_PER_BLOCK 8
#define UNROLL 8

__device__ unsigned int g_chunk_counter;

__global__ void zero_kernel(float4* __restrict__ out, int n4) {
    int i = blockIdx.x * blockDim.x + threadIdx.x;
    if (i == 0) g_chunk_counter = 0;   // reset work queue every launch/replay
    if (i < n4) out[i] = make_float4(0.f, 0.f, 0.f, 0.f);
}

// One vectorized fp32x4 reduction instead of 4 scalar atomics (sm_90+).
__device__ __forceinline__ void flush_acc(float* __restrict__ out, int seg,
                                          int lane, float4 a) {
    float* p = out + (long long)seg * FEAT + lane * 4;
    asm volatile("red.global.add.v4.f32 [%0], {%1, %2, %3, %4};"
                 :: "l"(p), "f"(a.x), "f"(a.y), "f"(a.z), "f"(a.w)
                 : "memory");
}

// STRIDE = 2: batch is int64 (read low 32-bit word); STRIDE = 1: int32.
template <int STRIDE, bool FULL>
__device__ __forceinline__ void run_chunk(const float4* __restrict__ hp,
                                          const int* __restrict__ bp,
                                          float* __restrict__ out,
                                          int rows, int lane) {
    int seg = __ldg(bp);
    float4 acc = make_float4(0.f, 0.f, 0.f, 0.f);

    #pragma unroll 1
    for (int r = 0; r < (FULL ? RPW : rows); r += UNROLL) {
        float4 v[UNROLL];
        int bb[UNROLL];
        // Front-batched independent loads for MLP; streaming hint on h
        // (never reused -> don't thrash L2).
        #pragma unroll
        for (int j = 0; j < UNROLL; j++) {
            if (FULL || r + j < rows) {
                v[j]  = __ldcs(hp + (long long)(r + j) * (FEAT / 4));
                bb[j] = __ldg(bp + (long long)(r + j) * STRIDE);
            }
        }
        #pragma unroll
        for (int j = 0; j < UNROLL; j++) {
            if (FULL || r + j < rows) {
                if (bb[j] != seg) {
                    flush_acc(out, seg, lane, acc);
                    acc = make_float4(0.f, 0.f, 0.f, 0.f);
                    seg = bb[j];
                }
                acc.x += v[j].x;
                acc.y += v[j].y;
                acc.z += v[j].z;
                acc.w += v[j].w;
            }
        }
    }
    flush_acc(out, seg, lane, acc);
}

template <int STRIDE>
__device__ __forceinline__ void work_loop(const float4* __restrict__ h,
                                          const int* __restrict__ b32,
                                          float* __restrict__ out,
                                          int n, int lane,
                                          unsigned int nchunks) {
    for (;;) {
        unsigned int c;
        if (lane == 0) c = atomicAdd(&g_chunk_counter, 1u);
        c = __shfl_sync(0xFFFFFFFFu, c, 0);
        if (c >= nchunks) return;

        const long long row0 = (long long)c * RPW;
        const float4* hp = h + row0 * (FEAT / 4) + lane;
        const int* bp = b32 + row0 * STRIDE;
        const long long rem = n - row0;
        if (rem >= RPW) run_chunk<STRIDE, true>(hp, bp, out, RPW, lane);
        else            run_chunk<STRIDE, false>(hp, bp, out, (int)rem, lane);
    }
}

__global__ void __launch_bounds__(WARPS_PER_BLOCK * 32)
segsum_kernel(const float4* __restrict__ h, const int* __restrict__ b32,
              float* __restrict__ out, int n) {
    const int lane = threadIdx.x;
    const unsigned int nchunks = (unsigned int)((n + RPW - 1) / RPW);

    // Dtype probe: batch is sorted, values in [0, 10000). Little-endian int64
    // -> odd 32-bit words are zero high-words; int32 -> odd words in the upper
    // half of the sorted array are ~5000..9999. L2-broadcast, ~free per warp.
    const int i1 = (n / 2) | 1;
    const int i2 = (n / 2 + n / 5) | 1;
    const int i3 = (n - 16) | 1;
    const bool is64 = (__ldg(b32 + i1) == 0) && (__ldg(b32 + i2) == 0) &&
                      (__ldg(b32 + i3) == 0);

    if (is64) work_loop<2>(h, b32, out, n, lane, nchunks);
    else      work_loop<1>(h, b32, out, n, lane, nchunks);
}

extern "C" void kernel_launch(void* const* d_in, const int* in_sizes, int n_in,
                              void* d_out, int out_size) {
    const float* h = (const float*)d_in[0];   // h_t [n, 128] f32
    const int* b32 = (const int*)d_in[1];     // batch [n] (int32 or int64)
    float* out = (float*)d_out;               // [10000, 128] f32
    const int n = in_sizes[1];

    const int n4 = out_size / 4;
    zero_kernel<<<(n4 + 255) / 256, 256>>>((float4*)out, n4);

    // One resident wave of persistent blocks: 152 SMs x 4 blocks (regs ~62
    // -> 4 CTAs/SM). Work distribution is via the atomic chunk queue, so an
    // exact match isn't required for correctness.
    const int nblocks = 152 * 4;
    dim3 bd(32, WARPS_PER_BLOCK);
    segsum_kernel<<<nblocks, bd>>>((const float4*)h, b32, out, n);
}

// round 4
// speedup vs baseline: 1.7525x; 1.7525x over previous
#include <cuda_runtime.h>

#define FEAT 128
#define RPW 208           // rows per warp: 4808 warps for n=1e6 -> exactly one
                          // resident wave (152 SMs x 4 CTAs x 8 warps = 4864)
#define WARPS_PER_BLOCK 8
#define UNROLL 8

__global__ void zero_kernel(float4* __restrict__ out, int n4) {
    int i = blockIdx.x * blockDim.x + threadIdx.x;
    if (i < n4) out[i] = make_float4(0.f, 0.f, 0.f, 0.f);
}

// One vectorized fp32x4 reduction instead of 4 scalar atomics (sm_90+).
__device__ __forceinline__ void flush_acc(float* __restrict__ out, int seg,
                                          int lane, float4 a) {
    float* p = out + (long long)seg * FEAT + lane * 4;
    asm volatile("red.global.add.v4.f32 [%0], {%1, %2, %3, %4};"
                 :: "l"(p), "f"(a.x), "f"(a.y), "f"(a.z), "f"(a.w)
                 : "memory");
}

// STRIDE = 2: batch is int64 (read low 32-bit word); STRIDE = 1: int32.
template <int STRIDE, bool FULL>
__device__ __forceinline__ void run_chunk(const float4* __restrict__ hp,
                                          const int* __restrict__ bp,
                                          float* __restrict__ out,
                                          int rows, int lane) {
    int seg = __ldg(bp);
    float4 acc = make_float4(0.f, 0.f, 0.f, 0.f);

    #pragma unroll 1
    for (int r = 0; r < (FULL ? RPW : rows); r += UNROLL) {
        float4 v[UNROLL];
        int bb[UNROLL];
        // Front-batched independent loads for MLP; streaming hint on h
        // (never reused -> don't thrash L2).
        #pragma unroll
        for (int j = 0; j < UNROLL; j++) {
            if (FULL || r + j < rows) {
                v[j]  = __ldcs(hp + (long long)(r + j) * (FEAT / 4));
                bb[j] = __ldg(bp + (long long)(r + j) * STRIDE);
            }
        }
        #pragma unroll
        for (int j = 0; j < UNROLL; j++) {
            if (FULL || r + j < rows) {
                if (bb[j] != seg) {
                    flush_acc(out, seg, lane, acc);
                    acc = make_float4(0.f, 0.f, 0.f, 0.f);
                    seg = bb[j];
                }
                acc.x += v[j].x;
                acc.y += v[j].y;
                acc.z += v[j].z;
                acc.w += v[j].w;
            }
        }
    }
    flush_acc(out, seg, lane, acc);
}

template <int STRIDE>
__device__ __forceinline__ void run_warp(const float4* __restrict__ h,
                                         const int* __restrict__ b32,
                                         float* __restrict__ out,
                                         int n, int lane, long long row0) {
    const float4* hp = h + row0 * (FEAT / 4) + lane;
    const int* bp = b32 + row0 * STRIDE;
    if (n - row0 >= RPW) {
        run_chunk<STRIDE, true>(hp, bp, out, RPW, lane);
    } else {
        run_chunk<STRIDE, false>(hp, bp, out, (int)(n - row0), lane);
    }
}

__global__ void __launch_bounds__(WARPS_PER_BLOCK * 32)
segsum_kernel(const float4* __restrict__ h, const int* __restrict__ b32,
              float* __restrict__ out, int n) {
    const int lane = threadIdx.x;
    const long long warp = (long long)blockIdx.x * WARPS_PER_BLOCK + threadIdx.y;
    const long long row0 = warp * RPW;
    if (row0 >= n) return;

    // Dtype probe: batch is sorted, values in [0, 10000). Little-endian int64
    // -> odd 32-bit words are zero high-words; int32 -> odd words in the upper
    // half of the sorted array are ~5000..9999. L2-broadcast, ~free per warp.
    const int i1 = (n / 2) | 1;
    const int i2 = (n / 2 + n / 5) | 1;
    const int i3 = (n - 16) | 1;
    const bool is64 = (__ldg(b32 + i1) == 0) && (__ldg(b32 + i2) == 0) &&
                      (__ldg(b32 + i3) == 0);

    if (is64) run_warp<2>(h, b32, out, n, lane, row0);
    else      run_warp<1>(h, b32, out, n, lane, row0);
}

extern "C" void kernel_launch(void* const* d_in, const int* in_sizes, int n_in,
                              void* d_out, int out_size) {
    const float* h = (const float*)d_in[0];   // h_t [n, 128] f32
    const int* b32 = (const int*)d_in[1];     // batch [n] (int32 or int64)
    float* out = (float*)d_out;               // [10000, 128] f32
    const int n = in_sizes[1];

    const int n4 = out_size / 4;
    zero_kernel<<<(n4 + 255) / 256, 256>>>((float4*)out, n4);

    const long long nwarps = ((long long)n + RPW - 1) / RPW;   // 4808 for n=1e6
    const int nblocks = (int)((nwarps + WARPS_PER_BLOCK - 1) / WARPS_PER_BLOCK);
    dim3 bd(32, WARPS_PER_BLOCK);
    segsum_kernel<<<nblocks, bd>>>((const float4*)h, b32, out, n);
}